// round 1
// baseline (speedup 1.0000x reference)
#include <cuda_runtime.h>
#include <math.h>

// ---------------------------------------------------------------------------
// ALiBi MHA with LoRA linears, fp32 baseline.
// Key identity: x@W.T + b + (x@A.T)@Bm.T*(alpha/r) == x@(W + (alpha/r)*Bm@A).T + b
// so each LoRA linear is ONE gemm against a precomputed effective weight.
// ---------------------------------------------------------------------------

#define E_DIM   1024
#define K_DIM   1024
#define S_LEN   2048
#define BATCH   2
#define NHEAD   16
#define HDIM    64
#define M_TOK   (BATCH * S_LEN)      // 4096 tokens

// Scratch (static device globals; allocation inside kernel_launch is forbidden)
__device__ float g_Weff [3u * 1024u * 1024u];  // q,k,v effective weights, concat
__device__ float g_WeffO[1024u * 1024u];       // o effective weight
__device__ float g_bqkv [3 * E_DIM];           // concat biases for qkv gemm
__device__ float g_QKV  [(size_t)M_TOK * 3 * E_DIM]; // [4096, 3072]
__device__ float g_Attn [(size_t)M_TOK * E_DIM];     // attention output [4096,1024]

// ---------------------------------------------------------------------------
// Kernel 1: W_eff = W + 0.125 * (Bm @ A)   (Bm:[1024,8], A:[8,1024])
// Also concatenates the qkv biases.
// ---------------------------------------------------------------------------
__global__ void build_weff_kernel(
    const float* __restrict__ Wq, const float* __restrict__ Aq, const float* __restrict__ Bq,
    const float* __restrict__ Wk, const float* __restrict__ Ak, const float* __restrict__ Bk,
    const float* __restrict__ Wv, const float* __restrict__ Av, const float* __restrict__ Bv,
    const float* __restrict__ Wo, const float* __restrict__ Ao, const float* __restrict__ Bo,
    const float* __restrict__ bq, const float* __restrict__ bk, const float* __restrict__ bv)
{
    int idx = blockIdx.x * blockDim.x + threadIdx.x;   // 0 .. 4M-1
    int w = idx >> 20;
    int e = idx & ((1 << 20) - 1);
    int i = e >> 10;
    int j = e & 1023;

    const float *W, *A, *Bm;
    float* out;
    if (w == 0)      { W = Wq; A = Aq; Bm = Bq; out = g_Weff; }
    else if (w == 1) { W = Wk; A = Ak; Bm = Bk; out = g_Weff + (1u << 20); }
    else if (w == 2) { W = Wv; A = Av; Bm = Bv; out = g_Weff + (2u << 20); }
    else             { W = Wo; A = Ao; Bm = Bo; out = g_WeffO; }

    float s = 0.f;
#pragma unroll
    for (int k = 0; k < 8; k++) s += Bm[i * 8 + k] * A[k * 1024 + j];
    out[e] = W[e] + 0.125f * s;   // alpha / r = 1/8

    if (idx < E_DIM) {
        g_bqkv[idx]            = bq[idx];
        g_bqkv[E_DIM + idx]    = bk[idx];
        g_bqkv[2 * E_DIM + idx] = bv[idx];
    }
}

// ---------------------------------------------------------------------------
// Kernel 2: SGEMM  Y[M,N] = X[M,K] @ W[N,K]^T (+ bias), optional residual
// epilogue Y = resid + rezero*(acc + bias).  128x128x16 tile, 8x8 per thread.
// M, K fixed (4096, 1024); N and pointers runtime.
// ---------------------------------------------------------------------------
#define BM 128
#define BN 128
#define BK 16

__global__ __launch_bounds__(256) void sgemm_nt_kernel(
    const float* __restrict__ X, const float* __restrict__ W,
    const float* __restrict__ bias, float* __restrict__ Y, int N,
    const float* __restrict__ resid, const float* __restrict__ rezero)
{
    __shared__ float As[BK][BM];
    __shared__ float Bs[BK][BN];

    const int tid = threadIdx.x;
    const int tn = tid & 15;        // 0..15 (N dir)
    const int tm = tid >> 4;        // 0..15 (M dir)
    const int bx = blockIdx.x;      // N tile
    const int by = blockIdx.y;      // M tile

    // global->smem loader mapping: 128 rows x 16 cols, each thread 4x float4
    const int lr = tid >> 2;          // 0..63
    const int lc = (tid & 3) << 2;    // 0,4,8,12

    const float* Xp = X + (size_t)(by * BM + lr) * K_DIM + lc;
    const float* Wp = W + (size_t)(bx * BN + lr) * K_DIM + lc;

    float acc[8][8];
#pragma unroll
    for (int i = 0; i < 8; i++)
#pragma unroll
        for (int j = 0; j < 8; j++) acc[i][j] = 0.f;

    for (int k0 = 0; k0 < K_DIM; k0 += BK) {
        float4 xa = *(const float4*)(Xp + k0);
        float4 xb = *(const float4*)(Xp + (size_t)64 * K_DIM + k0);
        float4 wa = *(const float4*)(Wp + k0);
        float4 wb = *(const float4*)(Wp + (size_t)64 * K_DIM + k0);
        __syncthreads();   // previous iteration's compute must finish
        As[lc + 0][lr] = xa.x; As[lc + 1][lr] = xa.y; As[lc + 2][lr] = xa.z; As[lc + 3][lr] = xa.w;
        As[lc + 0][lr + 64] = xb.x; As[lc + 1][lr + 64] = xb.y; As[lc + 2][lr + 64] = xb.z; As[lc + 3][lr + 64] = xb.w;
        Bs[lc + 0][lr] = wa.x; Bs[lc + 1][lr] = wa.y; Bs[lc + 2][lr] = wa.z; Bs[lc + 3][lr] = wa.w;
        Bs[lc + 0][lr + 64] = wb.x; Bs[lc + 1][lr + 64] = wb.y; Bs[lc + 2][lr + 64] = wb.z; Bs[lc + 3][lr + 64] = wb.w;
        __syncthreads();

#pragma unroll
        for (int kk = 0; kk < BK; kk++) {
            float a[8], b[8];
            *(float4*)&a[0] = *(const float4*)&As[kk][tm * 8];
            *(float4*)&a[4] = *(const float4*)&As[kk][tm * 8 + 4];
            *(float4*)&b[0] = *(const float4*)&Bs[kk][tn * 8];
            *(float4*)&b[4] = *(const float4*)&Bs[kk][tn * 8 + 4];
#pragma unroll
            for (int i = 0; i < 8; i++)
#pragma unroll
                for (int j = 0; j < 8; j++)
                    acc[i][j] += a[i] * b[j];
        }
    }

    const int ncol = bx * BN + tn * 8;
    float bv[8];
#pragma unroll
    for (int j = 0; j < 8; j++) bv[j] = bias[ncol + j];

    if (resid) {
        const float rz = rezero[0];
#pragma unroll
        for (int i = 0; i < 8; i++) {
            const int row = by * BM + tm * 8 + i;
            float* Yr = Y + (size_t)row * N + ncol;
            const float* Rr = resid + (size_t)row * N + ncol;
            float4 o0, o1;
            o0.x = Rr[0] + rz * (acc[i][0] + bv[0]);
            o0.y = Rr[1] + rz * (acc[i][1] + bv[1]);
            o0.z = Rr[2] + rz * (acc[i][2] + bv[2]);
            o0.w = Rr[3] + rz * (acc[i][3] + bv[3]);
            o1.x = Rr[4] + rz * (acc[i][4] + bv[4]);
            o1.y = Rr[5] + rz * (acc[i][5] + bv[5]);
            o1.z = Rr[6] + rz * (acc[i][6] + bv[6]);
            o1.w = Rr[7] + rz * (acc[i][7] + bv[7]);
            *(float4*)(Yr)     = o0;
            *(float4*)(Yr + 4) = o1;
        }
    } else {
#pragma unroll
        for (int i = 0; i < 8; i++) {
            const int row = by * BM + tm * 8 + i;
            float* Yr = Y + (size_t)row * N + ncol;
            float4 o0, o1;
            o0.x = acc[i][0] + bv[0]; o0.y = acc[i][1] + bv[1];
            o0.z = acc[i][2] + bv[2]; o0.w = acc[i][3] + bv[3];
            o1.x = acc[i][4] + bv[4]; o1.y = acc[i][5] + bv[5];
            o1.z = acc[i][6] + bv[6]; o1.w = acc[i][7] + bv[7];
            *(float4*)(Yr)     = o0;
            *(float4*)(Yr + 4) = o1;
        }
    }
}

// ---------------------------------------------------------------------------
// Kernel 3: ALiBi attention, fp32, online softmax.
// One thread = one query row (q,acc in registers). 32-key K/V tiles in smem.
// score(i,j) = (Q·K)/8 + slope_h*(j - i); softmax over ALL j (no mask).
// ---------------------------------------------------------------------------
__global__ __launch_bounds__(128) void attn_kernel()
{
    const int E3 = 3 * E_DIM;
    const int h = blockIdx.y;
    const int b = blockIdx.z;
    const int q = blockIdx.x * 128 + threadIdx.x;

    const float* base = g_QKV + (size_t)b * S_LEN * E3;

    float qreg[HDIM];
    {
        const float* Qp = base + (size_t)q * E3 + h * HDIM;
#pragma unroll
        for (int d = 0; d < HDIM; d += 4) {
            float4 t = *(const float4*)(Qp + d);
            qreg[d]     = t.x * 0.125f;   // fold 1/sqrt(64) into q
            qreg[d + 1] = t.y * 0.125f;
            qreg[d + 2] = t.z * 0.125f;
            qreg[d + 3] = t.w * 0.125f;
        }
    }
    const float slope = exp2f(-(float)h);   // 0.5^h
    const float fq = (float)q;

    float m = -1e30f, l = 0.f;
    float acc[HDIM];
#pragma unroll
    for (int d = 0; d < HDIM; d++) acc[d] = 0.f;

    __shared__ float Ks[32][HDIM];
    __shared__ float Vs[32][HDIM];

    const int r = threadIdx.x >> 2;         // 0..31
    const int c = (threadIdx.x & 3) << 4;   // 0,16,32,48

    for (int k0 = 0; k0 < S_LEN; k0 += 32) {
        __syncthreads();
        const float* Kp = base + (size_t)(k0 + r) * E3 + E_DIM + h * HDIM + c;
        const float* Vp = Kp + E_DIM;
#pragma unroll
        for (int u = 0; u < 16; u += 4) {
            *(float4*)&Ks[r][c + u] = *(const float4*)(Kp + u);
            *(float4*)&Vs[r][c + u] = *(const float4*)(Vp + u);
        }
        __syncthreads();

#pragma unroll 2
        for (int kk = 0; kk < 32; kk++) {
            float s0 = 0, s1 = 0, s2 = 0, s3 = 0, s4 = 0, s5 = 0, s6 = 0, s7 = 0;
#pragma unroll
            for (int d = 0; d < HDIM; d += 8) {
                s0 += qreg[d]     * Ks[kk][d];
                s1 += qreg[d + 1] * Ks[kk][d + 1];
                s2 += qreg[d + 2] * Ks[kk][d + 2];
                s3 += qreg[d + 3] * Ks[kk][d + 3];
                s4 += qreg[d + 4] * Ks[kk][d + 4];
                s5 += qreg[d + 5] * Ks[kk][d + 5];
                s6 += qreg[d + 6] * Ks[kk][d + 6];
                s7 += qreg[d + 7] * Ks[kk][d + 7];
            }
            float s = slope * ((float)(k0 + kk) - fq)
                    + ((s0 + s1) + (s2 + s3)) + ((s4 + s5) + (s6 + s7));
            float mn   = fmaxf(m, s);
            float corr = __expf(m - mn);
            float p    = __expf(s - mn);
            m = mn;
            l = l * corr + p;
#pragma unroll
            for (int d = 0; d < HDIM; d++)
                acc[d] = acc[d] * corr + p * Vs[kk][d];
        }
    }

    const float inv = 1.f / l;
    float* Op = g_Attn + ((size_t)(b * S_LEN + q)) * E_DIM + h * HDIM;
#pragma unroll
    for (int d = 0; d < HDIM; d += 4) {
        float4 t;
        t.x = acc[d] * inv; t.y = acc[d + 1] * inv;
        t.z = acc[d + 2] * inv; t.w = acc[d + 3] * inv;
        *(float4*)(Op + d) = t;
    }
}

// ---------------------------------------------------------------------------
// Launch
// ---------------------------------------------------------------------------
extern "C" void kernel_launch(void* const* d_in, const int* in_sizes, int n_in,
                              void* d_out, int out_size)
{
    const float* x   = (const float*)d_in[0];
    const float* Wq  = (const float*)d_in[1];
    const float* bq  = (const float*)d_in[2];
    const float* Aq  = (const float*)d_in[3];
    const float* Bq  = (const float*)d_in[4];
    const float* Wk  = (const float*)d_in[5];
    const float* bk  = (const float*)d_in[6];
    const float* Ak  = (const float*)d_in[7];
    const float* Bk  = (const float*)d_in[8];
    const float* Wv  = (const float*)d_in[9];
    const float* bv  = (const float*)d_in[10];
    const float* Av  = (const float*)d_in[11];
    const float* Bv  = (const float*)d_in[12];
    const float* Wo  = (const float*)d_in[13];
    const float* bo  = (const float*)d_in[14];
    const float* Aol = (const float*)d_in[15];
    const float* Bol = (const float*)d_in[16];
    const float* rez = (const float*)d_in[17];

    float* out = (float*)d_out;

    // device pointers to scratch globals (resolved via a kernel-visible symbol;
    // kernels reference the globals directly, so we only need launch params)
    float* g_weff_p;  cudaGetSymbolAddress((void**)&g_weff_p,  g_Weff);
    float* g_weffo_p; cudaGetSymbolAddress((void**)&g_weffo_p, g_WeffO);
    float* g_bqkv_p;  cudaGetSymbolAddress((void**)&g_bqkv_p,  g_bqkv);
    float* g_qkv_p;   cudaGetSymbolAddress((void**)&g_qkv_p,   g_QKV);
    float* g_attn_p;  cudaGetSymbolAddress((void**)&g_attn_p,  g_Attn);

    // 1) effective weights + bias concat
    build_weff_kernel<<<(4u * 1024u * 1024u) / 256, 256>>>(
        Wq, Aq, Bq, Wk, Ak, Bk, Wv, Av, Bv, Wo, Aol, Bol, bq, bk, bv);

    // 2) fused QKV projection: [4096,1024] @ [3072,1024]^T -> [4096,3072]
    {
        dim3 grid(3 * E_DIM / BN, M_TOK / BM);
        sgemm_nt_kernel<<<grid, 256>>>(x, g_weff_p, g_bqkv_p, g_qkv_p,
                                       3 * E_DIM, nullptr, nullptr);
    }

    // 3) attention
    {
        dim3 grid(S_LEN / 128, NHEAD, BATCH);
        attn_kernel<<<grid, 128>>>();
    }

    // 4) output projection + residual: out = x + rezero*(attn @ WeffO^T + bo)
    {
        dim3 grid(E_DIM / BN, M_TOK / BM);
        sgemm_nt_kernel<<<grid, 256>>>(g_attn_p, g_weffo_p, bo, out,
                                       E_DIM, x, rez);
    }
}

// round 2
// speedup vs baseline: 2.5833x; 2.5833x over previous
#include <cuda_runtime.h>
#include <cuda_fp16.h>
#include <math.h>

// ---------------------------------------------------------------------------
// ALiBi MHA with LoRA linears.
// LoRA identity: x@W.T + b + (x@A.T)@Bm.T*(alpha/r) == x@(W + (alpha/r)*Bm@A).T + b
// Pipeline: build Weff -> fused QKV sgemm (fp32) -> fp32->fp16 convert
//           -> FA2-style fp16 tensor-core attention -> O-proj sgemm + residual.
// ---------------------------------------------------------------------------

#define E_DIM   1024
#define K_DIM   1024
#define S_LEN   2048
#define BATCH   2
#define NHEAD   16
#define HDIM    64
#define M_TOK   (BATCH * S_LEN)      // 4096 tokens
#define LOG2E   1.44269504088896340736f

// Scratch (static device globals; allocation inside kernel_launch is forbidden)
__device__ float  g_Weff [3u * 1024u * 1024u];  // q,k,v effective weights, concat
__device__ float  g_WeffO[1024u * 1024u];       // o effective weight
__device__ float  g_bqkv [3 * E_DIM];           // concat biases for qkv gemm
__device__ float  g_QKV  [(size_t)M_TOK * 3 * E_DIM]; // [4096, 3072]
__device__ float  g_Attn [(size_t)M_TOK * E_DIM];     // attention output [4096,1024]
__device__ __half g_Qh   [(size_t)BATCH * NHEAD * S_LEN * HDIM]; // scaled by 0.125*log2e
__device__ __half g_Kh   [(size_t)BATCH * NHEAD * S_LEN * HDIM];
__device__ __half g_Vth  [(size_t)BATCH * NHEAD * HDIM * S_LEN]; // transposed [d][s]

// ---------------------------------------------------------------------------
// Kernel 1: W_eff = W + 0.125 * (Bm @ A)
// ---------------------------------------------------------------------------
__global__ void build_weff_kernel(
    const float* __restrict__ Wq, const float* __restrict__ Aq, const float* __restrict__ Bq,
    const float* __restrict__ Wk, const float* __restrict__ Ak, const float* __restrict__ Bk,
    const float* __restrict__ Wv, const float* __restrict__ Av, const float* __restrict__ Bv,
    const float* __restrict__ Wo, const float* __restrict__ Ao, const float* __restrict__ Bo,
    const float* __restrict__ bq, const float* __restrict__ bk, const float* __restrict__ bv)
{
    int idx = blockIdx.x * blockDim.x + threadIdx.x;   // 0 .. 4M-1
    int w = idx >> 20;
    int e = idx & ((1 << 20) - 1);
    int i = e >> 10;
    int j = e & 1023;

    const float *W, *A, *Bm;
    float* out;
    if (w == 0)      { W = Wq; A = Aq; Bm = Bq; out = g_Weff; }
    else if (w == 1) { W = Wk; A = Ak; Bm = Bk; out = g_Weff + (1u << 20); }
    else if (w == 2) { W = Wv; A = Av; Bm = Bv; out = g_Weff + (2u << 20); }
    else             { W = Wo; A = Ao; Bm = Bo; out = g_WeffO; }

    float s = 0.f;
#pragma unroll
    for (int k = 0; k < 8; k++) s += Bm[i * 8 + k] * A[k * 1024 + j];
    out[e] = W[e] + 0.125f * s;   // alpha / r = 1/8

    if (idx < E_DIM) {
        g_bqkv[idx]             = bq[idx];
        g_bqkv[E_DIM + idx]     = bk[idx];
        g_bqkv[2 * E_DIM + idx] = bv[idx];
    }
}

// ---------------------------------------------------------------------------
// Kernel 2: fp32 SGEMM  Y[M,N] = X[M,K] @ W[N,K]^T (+bias) [+ residual epi]
// ---------------------------------------------------------------------------
#define BM 128
#define BN 128
#define BK 16

__global__ __launch_bounds__(256) void sgemm_nt_kernel(
    const float* __restrict__ X, const float* __restrict__ W,
    const float* __restrict__ bias, float* __restrict__ Y, int N,
    const float* __restrict__ resid, const float* __restrict__ rezero)
{
    __shared__ float As[BK][BM];
    __shared__ float Bs[BK][BN];

    const int tid = threadIdx.x;
    const int tn = tid & 15;
    const int tm = tid >> 4;
    const int bx = blockIdx.x;
    const int by = blockIdx.y;

    const int lr = tid >> 2;
    const int lc = (tid & 3) << 2;

    const float* Xp = X + (size_t)(by * BM + lr) * K_DIM + lc;
    const float* Wp = W + (size_t)(bx * BN + lr) * K_DIM + lc;

    float acc[8][8];
#pragma unroll
    for (int i = 0; i < 8; i++)
#pragma unroll
        for (int j = 0; j < 8; j++) acc[i][j] = 0.f;

    for (int k0 = 0; k0 < K_DIM; k0 += BK) {
        float4 xa = *(const float4*)(Xp + k0);
        float4 xb = *(const float4*)(Xp + (size_t)64 * K_DIM + k0);
        float4 wa = *(const float4*)(Wp + k0);
        float4 wb = *(const float4*)(Wp + (size_t)64 * K_DIM + k0);
        __syncthreads();
        As[lc + 0][lr] = xa.x; As[lc + 1][lr] = xa.y; As[lc + 2][lr] = xa.z; As[lc + 3][lr] = xa.w;
        As[lc + 0][lr + 64] = xb.x; As[lc + 1][lr + 64] = xb.y; As[lc + 2][lr + 64] = xb.z; As[lc + 3][lr + 64] = xb.w;
        Bs[lc + 0][lr] = wa.x; Bs[lc + 1][lr] = wa.y; Bs[lc + 2][lr] = wa.z; Bs[lc + 3][lr] = wa.w;
        Bs[lc + 0][lr + 64] = wb.x; Bs[lc + 1][lr + 64] = wb.y; Bs[lc + 2][lr + 64] = wb.z; Bs[lc + 3][lr + 64] = wb.w;
        __syncthreads();

#pragma unroll
        for (int kk = 0; kk < BK; kk++) {
            float a[8], b[8];
            *(float4*)&a[0] = *(const float4*)&As[kk][tm * 8];
            *(float4*)&a[4] = *(const float4*)&As[kk][tm * 8 + 4];
            *(float4*)&b[0] = *(const float4*)&Bs[kk][tn * 8];
            *(float4*)&b[4] = *(const float4*)&Bs[kk][tn * 8 + 4];
#pragma unroll
            for (int i = 0; i < 8; i++)
#pragma unroll
                for (int j = 0; j < 8; j++)
                    acc[i][j] += a[i] * b[j];
        }
    }

    const int ncol = bx * BN + tn * 8;
    float bv[8];
#pragma unroll
    for (int j = 0; j < 8; j++) bv[j] = bias[ncol + j];

    if (resid) {
        const float rz = rezero[0];
#pragma unroll
        for (int i = 0; i < 8; i++) {
            const int row = by * BM + tm * 8 + i;
            float* Yr = Y + (size_t)row * N + ncol;
            const float* Rr = resid + (size_t)row * N + ncol;
            float4 o0, o1;
            o0.x = Rr[0] + rz * (acc[i][0] + bv[0]);
            o0.y = Rr[1] + rz * (acc[i][1] + bv[1]);
            o0.z = Rr[2] + rz * (acc[i][2] + bv[2]);
            o0.w = Rr[3] + rz * (acc[i][3] + bv[3]);
            o1.x = Rr[4] + rz * (acc[i][4] + bv[4]);
            o1.y = Rr[5] + rz * (acc[i][5] + bv[5]);
            o1.z = Rr[6] + rz * (acc[i][6] + bv[6]);
            o1.w = Rr[7] + rz * (acc[i][7] + bv[7]);
            *(float4*)(Yr)     = o0;
            *(float4*)(Yr + 4) = o1;
        }
    } else {
#pragma unroll
        for (int i = 0; i < 8; i++) {
            const int row = by * BM + tm * 8 + i;
            float* Yr = Y + (size_t)row * N + ncol;
            float4 o0, o1;
            o0.x = acc[i][0] + bv[0]; o0.y = acc[i][1] + bv[1];
            o0.z = acc[i][2] + bv[2]; o0.w = acc[i][3] + bv[3];
            o1.x = acc[i][4] + bv[4]; o1.y = acc[i][5] + bv[5];
            o1.z = acc[i][6] + bv[6]; o1.w = acc[i][7] + bv[7];
            *(float4*)(Yr)     = o0;
            *(float4*)(Yr + 4) = o1;
        }
    }
}

// ---------------------------------------------------------------------------
// Kernel 3: convert fused QKV fp32 -> fp16 buffers for attention.
// Q scaled by 0.125*log2e.  V written transposed [head][dim][token].
// grid (S/64, NHEAD, BATCH), 256 threads.
// ---------------------------------------------------------------------------
__global__ __launch_bounds__(256) void convert_qkv_kernel()
{
    const int tid = threadIdx.x;
    const int b = blockIdx.z, h = blockIdx.y;
    const int t0 = blockIdx.x * 64;
    const int bh = b * NHEAD + h;
    const float QSCALE = 0.125f * LOG2E;

    const float* src = g_QKV + (size_t)(b * S_LEN + t0) * (3 * E_DIM);

    // Q and K: copy-convert (row-major [token][64])
#pragma unroll 2
    for (int idx = tid; idx < 64 * 32; idx += 256) {
        int row = idx >> 5;
        int dp  = (idx & 31) * 2;
        const float* p = src + (size_t)row * (3 * E_DIM) + h * HDIM + dp;
        float2 qv = *(const float2*)(p);
        float2 kv = *(const float2*)(p + E_DIM);
        __half2 qh = __floats2half2_rn(qv.x * QSCALE, qv.y * QSCALE);
        __half2 kh = __floats2half2_rn(kv.x, kv.y);
        size_t o = (size_t)bh * S_LEN * HDIM + (size_t)(t0 + row) * HDIM + dp;
        *(unsigned*)&g_Qh[o] = *(unsigned*)&qh;
        *(unsigned*)&g_Kh[o] = *(unsigned*)&kh;
    }

    // V: transpose via smem
    __shared__ float vt[64][65];
#pragma unroll 2
    for (int idx = tid; idx < 64 * 16; idx += 256) {
        int row = idx >> 4;
        int c4  = (idx & 15) * 4;
        float4 v = *(const float4*)(src + (size_t)row * (3 * E_DIM) + 2 * E_DIM + h * HDIM + c4);
        vt[row][c4 + 0] = v.x; vt[row][c4 + 1] = v.y;
        vt[row][c4 + 2] = v.z; vt[row][c4 + 3] = v.w;
    }
    __syncthreads();
#pragma unroll 2
    for (int idx = tid; idx < 64 * 32; idx += 256) {
        int d  = idx >> 5;
        int tp = (idx & 31) * 2;
        __half2 vh = __floats2half2_rn(vt[tp][d], vt[tp + 1][d]);
        size_t o = (size_t)bh * HDIM * S_LEN + (size_t)d * S_LEN + t0 + tp;
        *(unsigned*)&g_Vth[o] = *(unsigned*)&vh;
    }
}

// ---------------------------------------------------------------------------
// Kernel 4: FA2-style attention with mma.sync m16n8k16 (fp16 in, fp32 accum).
// CTA = 4 warps, 64 queries (16/warp), key tiles of 64.
// Scores are in log2 domain (log2e folded into Q scale and slope).
// ---------------------------------------------------------------------------
__device__ __forceinline__ void mma16816(float c[4], const unsigned a[4],
                                         unsigned b0, unsigned b1)
{
    asm volatile(
        "mma.sync.aligned.m16n8k16.row.col.f32.f16.f16.f32 "
        "{%0,%1,%2,%3}, {%4,%5,%6,%7}, {%8,%9}, {%0,%1,%2,%3};"
        : "+f"(c[0]), "+f"(c[1]), "+f"(c[2]), "+f"(c[3])
        : "r"(a[0]), "r"(a[1]), "r"(a[2]), "r"(a[3]), "r"(b0), "r"(b1));
}

__global__ __launch_bounds__(128) void attn_mma_kernel()
{
    const int w    = threadIdx.x >> 5;
    const int lane = threadIdx.x & 31;
    const int g    = lane >> 2;          // groupID (row within 8 / n within 8)
    const int qq2  = (lane & 3) * 2;     // threadID_in_group*2
    const int h = blockIdx.y, b = blockIdx.z;
    const int bh = b * NHEAD + h;
    const int q0 = blockIdx.x * 64 + w * 16;
    const int gq0 = q0 + g, gq1 = gq0 + 8;

    __shared__ __align__(16) __half Ks[64 * 64];
    __shared__ __align__(16) __half Vs[64 * 64];

    const __half* Qp = g_Qh  + (size_t)bh * S_LEN * HDIM;
    const __half* Kp = g_Kh  + (size_t)bh * S_LEN * HDIM;
    const __half* Vp = g_Vth + (size_t)bh * HDIM * S_LEN;

    // Q fragments (resident across the whole key loop)
    unsigned qA[4][4];
    {
        const __half* qr0 = Qp + (size_t)gq0 * HDIM;
        const __half* qr1 = Qp + (size_t)gq1 * HDIM;
#pragma unroll
        for (int kb = 0; kb < 4; kb++) {
            qA[kb][0] = *(const unsigned*)(qr0 + kb * 16 + qq2);
            qA[kb][1] = *(const unsigned*)(qr1 + kb * 16 + qq2);
            qA[kb][2] = *(const unsigned*)(qr0 + kb * 16 + qq2 + 8);
            qA[kb][3] = *(const unsigned*)(qr1 + kb * 16 + qq2 + 8);
        }
    }

    const float slope2 = exp2f(-(float)h) * LOG2E;   // slope * log2e
    const float qb0 = slope2 * (float)gq0;
    const float qb1 = slope2 * (float)gq1;

    float Oacc[8][4];
#pragma unroll
    for (int i = 0; i < 8; i++)
#pragma unroll
        for (int j = 0; j < 4; j++) Oacc[i][j] = 0.f;
    float m0 = -INFINITY, m1 = -INFINITY, l0 = 0.f, l1 = 0.f;

    for (int kt = 0; kt < S_LEN; kt += 64) {
        __syncthreads();
        // load K tile [key][64] and V^T tile [dim][64keys], XOR-swizzled chunks
#pragma unroll
        for (int i = 0; i < 4; i++) {
            int ci = threadIdx.x + i * 128;       // 0..511 chunk index
            int row = ci >> 3, c = ci & 7;
            int sw = row * 64 + ((c ^ (row & 7)) << 3);
            *(uint4*)&Ks[sw] = *(const uint4*)(Kp + (size_t)(kt + row) * HDIM + c * 8);
            *(uint4*)&Vs[sw] = *(const uint4*)(Vp + (size_t)row * S_LEN + kt + c * 8);
        }
        __syncthreads();

        // S = Q @ K^T  (log2 domain)
        float S[8][4];
#pragma unroll
        for (int i = 0; i < 8; i++)
#pragma unroll
            for (int j = 0; j < 4; j++) S[i][j] = 0.f;
#pragma unroll
        for (int nb = 0; nb < 8; nb++) {
            int key = nb * 8 + g;
            int kx  = key & 7;
            int base = key * 64 + qq2;
#pragma unroll
            for (int kb = 0; kb < 4; kb++) {
                unsigned b0 = *(const unsigned*)&Ks[base + (((2 * kb)     ^ kx) << 3)];
                unsigned b1 = *(const unsigned*)&Ks[base + (((2 * kb + 1) ^ kx) << 3)];
                mma16816(S[nb], qA[kb], b0, b1);
            }
        }

        // ALiBi bias + row max
        float mt0 = -INFINITY, mt1 = -INFINITY;
#pragma unroll
        for (int nb = 0; nb < 8; nb++) {
            float kc = slope2 * (float)(kt + nb * 8 + qq2);
            S[nb][0] += kc - qb0;
            S[nb][1] += kc + slope2 - qb0;
            S[nb][2] += kc - qb1;
            S[nb][3] += kc + slope2 - qb1;
            mt0 = fmaxf(mt0, fmaxf(S[nb][0], S[nb][1]));
            mt1 = fmaxf(mt1, fmaxf(S[nb][2], S[nb][3]));
        }
        mt0 = fmaxf(mt0, __shfl_xor_sync(0xffffffffu, mt0, 1));
        mt0 = fmaxf(mt0, __shfl_xor_sync(0xffffffffu, mt0, 2));
        mt1 = fmaxf(mt1, __shfl_xor_sync(0xffffffffu, mt1, 1));
        mt1 = fmaxf(mt1, __shfl_xor_sync(0xffffffffu, mt1, 2));
        float nm0 = fmaxf(m0, mt0), nm1 = fmaxf(m1, mt1);
        float corr0 = exp2f(m0 - nm0), corr1 = exp2f(m1 - nm1);
        m0 = nm0; m1 = nm1;

        // P = exp2(S - m), pack to fp16 (C layout == next A layout)
        unsigned pr0[8], pr1[8];
        float ts0 = 0.f, ts1 = 0.f;
#pragma unroll
        for (int nb = 0; nb < 8; nb++) {
            float p00 = exp2f(S[nb][0] - m0);
            float p01 = exp2f(S[nb][1] - m0);
            float p10 = exp2f(S[nb][2] - m1);
            float p11 = exp2f(S[nb][3] - m1);
            ts0 += p00 + p01;
            ts1 += p10 + p11;
            __half2 h0 = __floats2half2_rn(p00, p01);
            __half2 h1 = __floats2half2_rn(p10, p11);
            pr0[nb] = *(unsigned*)&h0;
            pr1[nb] = *(unsigned*)&h1;
        }
        l0 = l0 * corr0 + ts0;
        l1 = l1 * corr1 + ts1;
#pragma unroll
        for (int nb = 0; nb < 8; nb++) {
            Oacc[nb][0] *= corr0; Oacc[nb][1] *= corr0;
            Oacc[nb][2] *= corr1; Oacc[nb][3] *= corr1;
        }

        // O += P @ V   (V^T in smem: B frag = contiguous half2 over keys)
#pragma unroll
        for (int nbO = 0; nbO < 8; nbO++) {
            int dim = nbO * 8 + g;
            int dx  = dim & 7;
            int base = dim * 64 + qq2;
#pragma unroll
            for (int kb = 0; kb < 4; kb++) {
                unsigned b0 = *(const unsigned*)&Vs[base + (((2 * kb)     ^ dx) << 3)];
                unsigned b1 = *(const unsigned*)&Vs[base + (((2 * kb + 1) ^ dx) << 3)];
                unsigned a[4] = {pr0[2 * kb], pr1[2 * kb], pr0[2 * kb + 1], pr1[2 * kb + 1]};
                mma16816(Oacc[nbO], a, b0, b1);
            }
        }
    }

    // finalize: reduce l across quad, normalize, write fp32
    l0 += __shfl_xor_sync(0xffffffffu, l0, 1);
    l0 += __shfl_xor_sync(0xffffffffu, l0, 2);
    l1 += __shfl_xor_sync(0xffffffffu, l1, 1);
    l1 += __shfl_xor_sync(0xffffffffu, l1, 2);
    const float inv0 = 1.f / l0, inv1 = 1.f / l1;

    float* O0 = g_Attn + (size_t)(b * S_LEN + gq0) * E_DIM + h * HDIM;
    float* O1 = g_Attn + (size_t)(b * S_LEN + gq1) * E_DIM + h * HDIM;
#pragma unroll
    for (int nb = 0; nb < 8; nb++) {
        float2 v0 = make_float2(Oacc[nb][0] * inv0, Oacc[nb][1] * inv0);
        float2 v1 = make_float2(Oacc[nb][2] * inv1, Oacc[nb][3] * inv1);
        *(float2*)(O0 + nb * 8 + qq2) = v0;
        *(float2*)(O1 + nb * 8 + qq2) = v1;
    }
}

// ---------------------------------------------------------------------------
// Launch
// ---------------------------------------------------------------------------
extern "C" void kernel_launch(void* const* d_in, const int* in_sizes, int n_in,
                              void* d_out, int out_size)
{
    const float* x   = (const float*)d_in[0];
    const float* Wq  = (const float*)d_in[1];
    const float* bq  = (const float*)d_in[2];
    const float* Aq  = (const float*)d_in[3];
    const float* Bq  = (const float*)d_in[4];
    const float* Wk  = (const float*)d_in[5];
    const float* bk  = (const float*)d_in[6];
    const float* Ak  = (const float*)d_in[7];
    const float* Bk  = (const float*)d_in[8];
    const float* Wv  = (const float*)d_in[9];
    const float* bv  = (const float*)d_in[10];
    const float* Av  = (const float*)d_in[11];
    const float* Bv  = (const float*)d_in[12];
    const float* Wo  = (const float*)d_in[13];
    const float* bo  = (const float*)d_in[14];
    const float* Aol = (const float*)d_in[15];
    const float* Bol = (const float*)d_in[16];
    const float* rez = (const float*)d_in[17];

    float* out = (float*)d_out;

    float* g_weff_p;  cudaGetSymbolAddress((void**)&g_weff_p,  g_Weff);
    float* g_weffo_p; cudaGetSymbolAddress((void**)&g_weffo_p, g_WeffO);
    float* g_bqkv_p;  cudaGetSymbolAddress((void**)&g_bqkv_p,  g_bqkv);
    float* g_qkv_p;   cudaGetSymbolAddress((void**)&g_qkv_p,   g_QKV);
    float* g_attn_p;  cudaGetSymbolAddress((void**)&g_attn_p,  g_Attn);

    // 1) effective weights + bias concat
    build_weff_kernel<<<(4u * 1024u * 1024u) / 256, 256>>>(
        Wq, Aq, Bq, Wk, Ak, Bk, Wv, Av, Bv, Wo, Aol, Bol, bq, bk, bv);

    // 2) fused QKV projection: [4096,1024] @ [3072,1024]^T -> [4096,3072]
    {
        dim3 grid(3 * E_DIM / BN, M_TOK / BM);
        sgemm_nt_kernel<<<grid, 256>>>(x, g_weff_p, g_bqkv_p, g_qkv_p,
                                       3 * E_DIM, nullptr, nullptr);
    }

    // 3) convert to fp16 (Q scaled, V transposed)
    {
        dim3 grid(S_LEN / 64, NHEAD, BATCH);
        convert_qkv_kernel<<<grid, 256>>>();
    }

    // 4) tensor-core attention
    {
        dim3 grid(S_LEN / 64, NHEAD, BATCH);
        attn_mma_kernel<<<grid, 128>>>();
    }

    // 5) output projection + residual: out = x + rezero*(attn @ WeffO^T + bo)
    {
        dim3 grid(E_DIM / BN, M_TOK / BM);
        sgemm_nt_kernel<<<grid, 256>>>(g_attn_p, g_weffo_p, bo, out,
                                       E_DIM, x, rez);
    }
}

// round 3
// speedup vs baseline: 7.5804x; 2.9343x over previous
#include <cuda_runtime.h>
#include <cuda_fp16.h>
#include <math.h>

// ---------------------------------------------------------------------------
// ALiBi MHA + LoRA.  All-fp16 tensor-core pipeline:
//  prep (Weff fp16, x fp16) -> HGEMM QKV (epilogue writes per-head fp16 Q/K/V)
//  -> FA2 mma attention (fp16 out) -> HGEMM O-proj (fp32 residual epilogue).
// LoRA identity: x@W.T + b + (x@A.T)@Bm.T/8 == x@(W + Bm@A/8).T + b
// ---------------------------------------------------------------------------

#define E_DIM   1024
#define S_LEN   2048
#define BATCH   2
#define NHEAD   16
#define HDIM    64
#define M_TOK   4096
#define LOG2E   1.44269504088896340736f
#define QSC     (0.125f * LOG2E)

__device__ __half g_Weffh [3u * 1024u * 1024u];   // [3072][1024]
__device__ __half g_WeffOh[1024u * 1024u];        // [1024][1024]
__device__ float  g_bqkv  [3 * E_DIM];
__device__ __half g_Xh    [(size_t)M_TOK * E_DIM];
__device__ __half g_Qh    [(size_t)BATCH * NHEAD * S_LEN * HDIM]; // (acc+b)*QSC
__device__ __half g_Kh    [(size_t)BATCH * NHEAD * S_LEN * HDIM];
__device__ __half g_Vh    [(size_t)BATCH * NHEAD * S_LEN * HDIM]; // row-major
__device__ __half g_Attnh [(size_t)M_TOK * E_DIM];

// ---------------------------------------------------------------------------
// PTX helpers
// ---------------------------------------------------------------------------
__device__ __forceinline__ unsigned sptr(const void* p) {
    return (unsigned)__cvta_generic_to_shared(p);
}
__device__ __forceinline__ void ldm_x4(unsigned r[4], unsigned addr) {
    asm volatile("ldmatrix.sync.aligned.m8n8.x4.shared.b16 {%0,%1,%2,%3}, [%4];"
                 : "=r"(r[0]), "=r"(r[1]), "=r"(r[2]), "=r"(r[3]) : "r"(addr));
}
__device__ __forceinline__ void ldm_x4t(unsigned r[4], unsigned addr) {
    asm volatile("ldmatrix.sync.aligned.m8n8.x4.trans.shared.b16 {%0,%1,%2,%3}, [%4];"
                 : "=r"(r[0]), "=r"(r[1]), "=r"(r[2]), "=r"(r[3]) : "r"(addr));
}
__device__ __forceinline__ void cpasync16(unsigned saddr, const void* g) {
    asm volatile("cp.async.ca.shared.global [%0], [%1], 16;" :: "r"(saddr), "l"(g));
}
__device__ __forceinline__ void cp_commit() {
    asm volatile("cp.async.commit_group;");
}
template <int N> __device__ __forceinline__ void cp_wait() {
    asm volatile("cp.async.wait_group %0;" :: "n"(N));
}
__device__ __forceinline__ void mma16816(float c[4], const unsigned a[4],
                                         unsigned b0, unsigned b1)
{
    asm volatile(
        "mma.sync.aligned.m16n8k16.row.col.f32.f16.f16.f32 "
        "{%0,%1,%2,%3}, {%4,%5,%6,%7}, {%8,%9}, {%0,%1,%2,%3};"
        : "+f"(c[0]), "+f"(c[1]), "+f"(c[2]), "+f"(c[3])
        : "r"(a[0]), "r"(a[1]), "r"(a[2]), "r"(a[3]), "r"(b0), "r"(b1));
}

// ---------------------------------------------------------------------------
// Kernel 1: prep.  idx<4M: Weff = W + (Bm@A)/8 -> fp16.  idx>=4M: x -> fp16.
// ---------------------------------------------------------------------------
__global__ void prep_kernel(
    const float* __restrict__ Wq, const float* __restrict__ Aq, const float* __restrict__ Bq,
    const float* __restrict__ Wk, const float* __restrict__ Ak, const float* __restrict__ Bk,
    const float* __restrict__ Wv, const float* __restrict__ Av, const float* __restrict__ Bv,
    const float* __restrict__ Wo, const float* __restrict__ Ao, const float* __restrict__ Bo,
    const float* __restrict__ bq, const float* __restrict__ bk, const float* __restrict__ bv,
    const float* __restrict__ x)
{
    int idx = blockIdx.x * blockDim.x + threadIdx.x;
    if (idx >= (4 << 20)) {                 // x convert
        int j = idx - (4 << 20);
        g_Xh[j] = __float2half(x[j]);
        return;
    }
    int w = idx >> 20;
    int e = idx & ((1 << 20) - 1);
    int i = e >> 10;
    int j = e & 1023;

    const float *W, *A, *Bm;
    __half* out;
    if (w == 0)      { W = Wq; A = Aq; Bm = Bq; out = g_Weffh; }
    else if (w == 1) { W = Wk; A = Ak; Bm = Bk; out = g_Weffh + (1u << 20); }
    else if (w == 2) { W = Wv; A = Av; Bm = Bv; out = g_Weffh + (2u << 20); }
    else             { W = Wo; A = Ao; Bm = Bo; out = g_WeffOh; }

    float s = 0.f;
#pragma unroll
    for (int k = 0; k < 8; k++) s += Bm[i * 8 + k] * A[k * 1024 + j];
    out[e] = __float2half(W[e] + 0.125f * s);

    if (idx < E_DIM) {
        g_bqkv[idx]             = bq[idx];
        g_bqkv[E_DIM + idx]     = bk[idx];
        g_bqkv[2 * E_DIM + idx] = bv[idx];
    }
}

// ---------------------------------------------------------------------------
// Kernel 2: HGEMM  C[M,N] = A[M,1024] @ B[N,1024]^T, fp16 in, fp32 acc.
// 128x128x32 CTA tile, 8 warps (2x4), warp tile 64x32, cp.async double buffer.
// MODE 0: QKV epilogue (bias, Q-scale, scatter to per-head fp16 Q/K/V).
// MODE 1: O-proj epilogue (fp32: out = resid + rez*(acc+bias)).
// ---------------------------------------------------------------------------
// smem tile layout: 128 rows x 32 halfs; pairs of rows share a 128B phys row,
// slot = ((row&1)*4 + chunk) ^ ((row>>1)&7)  (chunk = 16B unit) -> ldmatrix
// phases hit 8 distinct slots -> conflict-free.
__device__ __forceinline__ int swoff(int row, int chunk) {
    int pr = row >> 1;
    int slot = (((row & 1) << 2) | chunk) ^ (pr & 7);
    return pr * 64 + slot * 8;   // in halfs
}

template <int MODE>
__global__ __launch_bounds__(256) void hgemm_kernel(
    const __half* __restrict__ Aop, const __half* __restrict__ Bop,
    const float* __restrict__ bias,
    const float* __restrict__ resid, const float* __restrict__ rezero,
    float* __restrict__ OutF)
{
    __shared__ __half sm[16384];   // 2 stages x (A 4096 + B 4096) halfs = 32KB

    const int tid  = threadIdx.x;
    const int lane = tid & 31, wid = tid >> 5;
    const int wm = wid >> 2, wn = wid & 3;
    const int g  = lane >> 2, qq2 = (lane & 3) * 2;
    const int bx = blockIdx.x, by = blockIdx.y;

    const __half* Ag = Aop + (size_t)(by * 128) * 1024;
    const __half* Bg = Bop + (size_t)(bx * 128) * 1024;
    const unsigned smb = sptr(sm);

    // per-thread load slots: 2 chunks of A + 2 of B per stage
    const int cid0 = tid, cid1 = tid + 256;
    const int lr0 = cid0 >> 2, lc0 = cid0 & 3;
    const int lr1 = cid1 >> 2, lc1 = cid1 & 3;
    const unsigned sa0 = swoff(lr0, lc0) * 2u, sa1 = swoff(lr1, lc1) * 2u;

    float acc[4][4][4];
#pragma unroll
    for (int a = 0; a < 4; a++)
#pragma unroll
        for (int b = 0; b < 4; b++)
#pragma unroll
            for (int c = 0; c < 4; c++) acc[a][b][c] = 0.f;

#define ISSUE(KT, ST) do {                                                   \
    unsigned ab = smb + (ST) * 16384u;                                       \
    unsigned bb = ab + 8192u;                                                \
    int kb = (KT) * 32;                                                      \
    cpasync16(ab + sa0, Ag + (size_t)lr0 * 1024 + kb + lc0 * 8);             \
    cpasync16(ab + sa1, Ag + (size_t)lr1 * 1024 + kb + lc1 * 8);             \
    cpasync16(bb + sa0, Bg + (size_t)lr0 * 1024 + kb + lc0 * 8);             \
    cpasync16(bb + sa1, Bg + (size_t)lr1 * 1024 + kb + lc1 * 8);             \
    cp_commit();                                                             \
} while (0)

    ISSUE(0, 0);

    for (int kt = 0; kt < 32; kt++) {
        const int st = kt & 1;
        if (kt + 1 < 32) { ISSUE(kt + 1, st ^ 1); cp_wait<1>(); }
        else             { cp_wait<0>(); }
        __syncthreads();

        const unsigned ab = smb + st * 16384u;
        const unsigned bb = ab + 8192u;
#pragma unroll
        for (int ks = 0; ks < 2; ks++) {
            unsigned af[4][4];
#pragma unroll
            for (int mi = 0; mi < 4; mi++) {
                int row = wm * 64 + mi * 16 + (lane & 15);
                int ch  = ks * 2 + (lane >> 4);
                ldm_x4(af[mi], ab + swoff(row, ch) * 2u);
            }
            unsigned bf[2][4];
#pragma unroll
            for (int np = 0; np < 2; np++) {
                int row = wn * 32 + np * 16 + (lane & 15);
                int ch  = ks * 2 + (lane >> 4);
                ldm_x4(bf[np], bb + swoff(row, ch) * 2u);
            }
#pragma unroll
            for (int mi = 0; mi < 4; mi++)
#pragma unroll
                for (int np = 0; np < 2; np++) {
                    mma16816(acc[mi][np * 2],     af[mi], bf[np][0], bf[np][2]);
                    mma16816(acc[mi][np * 2 + 1], af[mi], bf[np][1], bf[np][3]);
                }
        }
        __syncthreads();
    }
#undef ISSUE

    if (MODE == 0) {
        // QKV scatter epilogue
        const int sec = (bx * 128) >> 10;                  // 0=q 1=k 2=v
        __half* dst = (sec == 0) ? g_Qh : (sec == 1) ? g_Kh : g_Vh;
        const float qs = (sec == 0) ? QSC : 1.f;
#pragma unroll
        for (int mi = 0; mi < 4; mi++) {
#pragma unroll
            for (int nb = 0; nb < 4; nb++) {
                const int colg = bx * 128 + wn * 32 + nb * 8 + qq2;
                const float b0v = bias[colg], b1v = bias[colg + 1];
                const int cc = colg & 1023;
                const int h = cc >> 6, d = cc & 63;
#pragma unroll
                for (int half = 0; half < 2; half++) {
                    const int r = by * 128 + wm * 64 + mi * 16 + g + half * 8;
                    const int bb2 = r >> 11, s = r & 2047;
                    __half2 hv = __floats2half2_rn(
                        (acc[mi][nb][half * 2]     + b0v) * qs,
                        (acc[mi][nb][half * 2 + 1] + b1v) * qs);
                    *(unsigned*)&dst[(((size_t)bb2 * NHEAD + h) * S_LEN + s) * HDIM + d] =
                        *(unsigned*)&hv;
                }
            }
        }
    } else {
        // O-proj residual epilogue
        const float rz = rezero[0];
#pragma unroll
        for (int mi = 0; mi < 4; mi++) {
#pragma unroll
            for (int nb = 0; nb < 4; nb++) {
                const int colg = bx * 128 + wn * 32 + nb * 8 + qq2;
                const float b0v = bias[colg], b1v = bias[colg + 1];
#pragma unroll
                for (int half = 0; half < 2; half++) {
                    const int r = by * 128 + wm * 64 + mi * 16 + g + half * 8;
                    float2 o;
                    o.x = resid[(size_t)r * 1024 + colg]     + rz * (acc[mi][nb][half * 2]     + b0v);
                    o.y = resid[(size_t)r * 1024 + colg + 1] + rz * (acc[mi][nb][half * 2 + 1] + b1v);
                    *(float2*)&OutF[(size_t)r * 1024 + colg] = o;
                }
            }
        }
    }
}

// ---------------------------------------------------------------------------
// Kernel 3: FA2 attention, mma m16n8k16, ALiBi in log2 domain.
// CTA = 4 warps, 64 queries, 64-key tiles.  V row-major, PV via ldmatrix.trans.
// ---------------------------------------------------------------------------
__global__ __launch_bounds__(128) void attn_mma_kernel()
{
    const int w    = threadIdx.x >> 5;
    const int lane = threadIdx.x & 31;
    const int g    = lane >> 2;
    const int qq2  = (lane & 3) * 2;
    const int h = blockIdx.y, b = blockIdx.z;
    const int bh = b * NHEAD + h;
    const int q0 = blockIdx.x * 64 + w * 16;
    const int gq0 = q0 + g, gq1 = gq0 + 8;

    __shared__ __align__(16) __half Ks[64 * 64];
    __shared__ __align__(16) __half Vs[64 * 64];

    const __half* Qp = g_Qh + (size_t)bh * S_LEN * HDIM;
    const __half* Kp = g_Kh + (size_t)bh * S_LEN * HDIM;
    const __half* Vp = g_Vh + (size_t)bh * S_LEN * HDIM;
    const unsigned vsb = sptr(Vs);

    unsigned qA[4][4];
    {
        const __half* qr0 = Qp + (size_t)gq0 * HDIM;
        const __half* qr1 = Qp + (size_t)gq1 * HDIM;
#pragma unroll
        for (int kb = 0; kb < 4; kb++) {
            qA[kb][0] = *(const unsigned*)(qr0 + kb * 16 + qq2);
            qA[kb][1] = *(const unsigned*)(qr1 + kb * 16 + qq2);
            qA[kb][2] = *(const unsigned*)(qr0 + kb * 16 + qq2 + 8);
            qA[kb][3] = *(const unsigned*)(qr1 + kb * 16 + qq2 + 8);
        }
    }

    const float slope2 = exp2f(-(float)h) * LOG2E;
    const float qb0 = slope2 * (float)gq0;
    const float qb1 = slope2 * (float)gq1;

    float Oacc[8][4];
#pragma unroll
    for (int i = 0; i < 8; i++)
#pragma unroll
        for (int j = 0; j < 4; j++) Oacc[i][j] = 0.f;
    float m0 = -INFINITY, m1 = -INFINITY, l0 = 0.f, l1 = 0.f;

    for (int kt = 0; kt < S_LEN; kt += 64) {
        __syncthreads();
#pragma unroll
        for (int i = 0; i < 4; i++) {
            int ci = threadIdx.x + i * 128;
            int row = ci >> 3, c = ci & 7;
            int sw = row * 64 + ((c ^ (row & 7)) << 3);
            *(uint4*)&Ks[sw] = *(const uint4*)(Kp + (size_t)(kt + row) * HDIM + c * 8);
            *(uint4*)&Vs[sw] = *(const uint4*)(Vp + (size_t)(kt + row) * HDIM + c * 8);
        }
        __syncthreads();

        // S = Q K^T
        float S[8][4];
#pragma unroll
        for (int i = 0; i < 8; i++)
#pragma unroll
            for (int j = 0; j < 4; j++) S[i][j] = 0.f;
#pragma unroll
        for (int nb = 0; nb < 8; nb++) {
            int key = nb * 8 + g;
            int kx  = key & 7;
            int base = key * 64 + qq2;
#pragma unroll
            for (int kb = 0; kb < 4; kb++) {
                unsigned b0 = *(const unsigned*)&Ks[base + (((2 * kb)     ^ kx) << 3)];
                unsigned b1 = *(const unsigned*)&Ks[base + (((2 * kb + 1) ^ kx) << 3)];
                mma16816(S[nb], qA[kb], b0, b1);
            }
        }

        // ALiBi + online softmax (log2 domain)
        float mt0 = -INFINITY, mt1 = -INFINITY;
#pragma unroll
        for (int nb = 0; nb < 8; nb++) {
            float kc = slope2 * (float)(kt + nb * 8 + qq2);
            S[nb][0] += kc - qb0;
            S[nb][1] += kc + slope2 - qb0;
            S[nb][2] += kc - qb1;
            S[nb][3] += kc + slope2 - qb1;
            mt0 = fmaxf(mt0, fmaxf(S[nb][0], S[nb][1]));
            mt1 = fmaxf(mt1, fmaxf(S[nb][2], S[nb][3]));
        }
        mt0 = fmaxf(mt0, __shfl_xor_sync(0xffffffffu, mt0, 1));
        mt0 = fmaxf(mt0, __shfl_xor_sync(0xffffffffu, mt0, 2));
        mt1 = fmaxf(mt1, __shfl_xor_sync(0xffffffffu, mt1, 1));
        mt1 = fmaxf(mt1, __shfl_xor_sync(0xffffffffu, mt1, 2));
        float nm0 = fmaxf(m0, mt0), nm1 = fmaxf(m1, mt1);
        float corr0 = exp2f(m0 - nm0), corr1 = exp2f(m1 - nm1);
        m0 = nm0; m1 = nm1;

        unsigned pr0[8], pr1[8];
        float ts0 = 0.f, ts1 = 0.f;
#pragma unroll
        for (int nb = 0; nb < 8; nb++) {
            float p00 = exp2f(S[nb][0] - m0);
            float p01 = exp2f(S[nb][1] - m0);
            float p10 = exp2f(S[nb][2] - m1);
            float p11 = exp2f(S[nb][3] - m1);
            ts0 += p00 + p01;
            ts1 += p10 + p11;
            __half2 h0 = __floats2half2_rn(p00, p01);
            __half2 h1 = __floats2half2_rn(p10, p11);
            pr0[nb] = *(unsigned*)&h0;
            pr1[nb] = *(unsigned*)&h1;
        }
        l0 = l0 * corr0 + ts0;
        l1 = l1 * corr1 + ts1;
#pragma unroll
        for (int nb = 0; nb < 8; nb++) {
            Oacc[nb][0] *= corr0; Oacc[nb][1] *= corr0;
            Oacc[nb][2] *= corr1; Oacc[nb][3] *= corr1;
        }

        // O += P @ V  via ldmatrix.x4.trans on row-major V tile
#pragma unroll
        for (int ks = 0; ks < 4; ks++) {
            unsigned a[4] = {pr0[2 * ks], pr1[2 * ks], pr0[2 * ks + 1], pr1[2 * ks + 1]};
#pragma unroll
            for (int dg = 0; dg < 4; dg++) {
                int row = ks * 16 + (lane & 7) + ((lane >> 3) & 1) * 8;
                int ch  = dg * 2 + (lane >> 4);
                unsigned addr = vsb + (unsigned)(row * 64 + ((ch ^ (row & 7)) << 3)) * 2u;
                unsigned t[4];
                ldm_x4t(t, addr);
                mma16816(Oacc[2 * dg],     a, t[0], t[1]);
                mma16816(Oacc[2 * dg + 1], a, t[2], t[3]);
            }
        }
    }

    l0 += __shfl_xor_sync(0xffffffffu, l0, 1);
    l0 += __shfl_xor_sync(0xffffffffu, l0, 2);
    l1 += __shfl_xor_sync(0xffffffffu, l1, 1);
    l1 += __shfl_xor_sync(0xffffffffu, l1, 2);
    const float inv0 = 1.f / l0, inv1 = 1.f / l1;

    __half* O0 = g_Attnh + (size_t)(b * S_LEN + gq0) * E_DIM + h * HDIM;
    __half* O1 = g_Attnh + (size_t)(b * S_LEN + gq1) * E_DIM + h * HDIM;
#pragma unroll
    for (int nb = 0; nb < 8; nb++) {
        __half2 v0 = __floats2half2_rn(Oacc[nb][0] * inv0, Oacc[nb][1] * inv0);
        __half2 v1 = __floats2half2_rn(Oacc[nb][2] * inv1, Oacc[nb][3] * inv1);
        *(unsigned*)(O0 + nb * 8 + qq2) = *(unsigned*)&v0;
        *(unsigned*)(O1 + nb * 8 + qq2) = *(unsigned*)&v1;
    }
}

// ---------------------------------------------------------------------------
// Launch
// ---------------------------------------------------------------------------
extern "C" void kernel_launch(void* const* d_in, const int* in_sizes, int n_in,
                              void* d_out, int out_size)
{
    const float* x   = (const float*)d_in[0];
    const float* Wq  = (const float*)d_in[1];
    const float* bq  = (const float*)d_in[2];
    const float* Aq  = (const float*)d_in[3];
    const float* Bq  = (const float*)d_in[4];
    const float* Wk  = (const float*)d_in[5];
    const float* bk  = (const float*)d_in[6];
    const float* Ak  = (const float*)d_in[7];
    const float* Bk  = (const float*)d_in[8];
    const float* Wv  = (const float*)d_in[9];
    const float* bv  = (const float*)d_in[10];
    const float* Av  = (const float*)d_in[11];
    const float* Bv  = (const float*)d_in[12];
    const float* Wo  = (const float*)d_in[13];
    const float* bo  = (const float*)d_in[14];
    const float* Aol = (const float*)d_in[15];
    const float* Bol = (const float*)d_in[16];
    const float* rez = (const float*)d_in[17];

    float* out = (float*)d_out;

    __half* xh_p;    cudaGetSymbolAddress((void**)&xh_p,    g_Xh);
    __half* weffh_p; cudaGetSymbolAddress((void**)&weffh_p, g_Weffh);
    __half* weffo_p; cudaGetSymbolAddress((void**)&weffo_p, g_WeffOh);
    float*  bqkv_p;  cudaGetSymbolAddress((void**)&bqkv_p,  g_bqkv);
    __half* attnh_p; cudaGetSymbolAddress((void**)&attnh_p, g_Attnh);

    // 1) Weff fp16 + x fp16
    prep_kernel<<<(8u << 20) / 256, 256>>>(
        Wq, Aq, Bq, Wk, Ak, Bk, Wv, Av, Bv, Wo, Aol, Bol, bq, bk, bv, x);

    // 2) QKV HGEMM [4096,1024]@[3072,1024]^T, scatter epilogue
    {
        dim3 grid(3 * E_DIM / 128, M_TOK / 128);
        hgemm_kernel<0><<<grid, 256>>>(xh_p, weffh_p, bqkv_p,
                                       nullptr, nullptr, nullptr);
    }

    // 3) attention
    {
        dim3 grid(S_LEN / 64, NHEAD, BATCH);
        attn_mma_kernel<<<grid, 128>>>();
    }

    // 4) O-proj HGEMM + residual
    {
        dim3 grid(E_DIM / 128, M_TOK / 128);
        hgemm_kernel<1><<<grid, 256>>>(attnh_p, weffo_p, bo, x, rez, out);
    }
}